// round 8
// baseline (speedup 1.0000x reference)
#include <cuda_runtime.h>
#include <cuda_fp16.h>
#include <stdint.h>

#define NT 4
#define P0 100
#define P1C 100
#define P2C 100

// W12 scratch, per (t,i1,i2) slice as TWO mma.m16n8k16 A-fragments
// (k = r1 0..15 / 16..31). Slice = 1KB. 41 MB -> L2-resident.
__device__ __align__(16) __half g_W12[(size_t)NT * P1C * P2C * 512];

// c0 as fp16 B-fragments: per (t,i0) slice, lane l holds uint4
// {b0_f0, b1_f0, b0_f1, b1_f1}. B[k=r1][n=q0], cols 4..7 zero. 204.8KB.
__device__ uint4 g_c0f[(size_t)NT * P0 * 32];

// ---- Blackwell packed fp32 helpers -----------------------------------------
#define FMA_F32X2(d, a, b, c) \
    asm("fma.rn.f32x2 %0, %1, %2, %3;" : "=l"(d) : "l"(a), "l"(b), "l"(c))

__device__ __forceinline__ unsigned long long pack2(float lo, float hi) {
    unsigned long long r;
    asm("mov.b64 %0, {%1, %2};" : "=l"(r) : "f"(lo), "f"(hi));
    return r;
}
__device__ __forceinline__ float2 unpack2(unsigned long long v) {
    float2 f;
    asm("mov.b64 {%0, %1}, %2;" : "=f"(f.x), "=f"(f.y) : "l"(v));
    return f;
}
// r = {hi:lo} packed fp16x2
__device__ __forceinline__ unsigned pack_h2(float lo, float hi) {
    unsigned r;
    asm("cvt.rn.f16x2.f32 %0, %1, %2;" : "=r"(r) : "f"(hi), "f"(lo));
    return r;
}

// c2t skewed layout: [q2][i2'][r2] with +8-float skew per q2 so the four
// q2-broadcast-groups hit bank offsets {0,8,16,24} -> conflict-free LDS.128.
#define C2T_Q2_STRIDE (50 * 32 + 8)   // 1608 floats

// ---------------------------------------------------------------------------
// Kernel 1 (fused): blocks 0..799 compute W12 fragments; blocks 800..803
// build the c0 B-fragments (one table each).
//
// W12 part: block = (t, i1, i2-half), 256 threads = (m = tid&15, kp = tid>>4).
// Warp w covers c1 rows 16w..16w+15 -> hoist LDGs are 8-line/4-lane-bcast.
// Thread computes W[m][2kp], W[m][2kp+1] = one .b32 A-reg (half2).
// ---------------------------------------------------------------------------
__global__ __launch_bounds__(256) void tt_precompute_kernel(
        const float* __restrict__ c1g, const float* __restrict__ c2g,
        const float* __restrict__ c0g) {
    int b = blockIdx.x;
    int tid = threadIdx.x;

    if (b >= NT * P1C * 2) {                   // ---- c0 fragment blocks ----
        int tt = b - NT * P1C * 2;             // table 0..3
        for (int task = tid; task < P0 * 32; task += 256) {
            int sl   = task >> 5;              // i0
            int lane = task & 31;              // == real lane (256 % 32 == 0)
            int g = lane >> 2, j = lane & 3;
            uint4 v = make_uint4(0u, 0u, 0u, 0u);
            if (g < 4) {
                const float* row = c0g + ((size_t)(tt * P0 + sl)) * 128 + g * 32 + 2 * j;
                float2 p0 = *(const float2*)(row);
                float2 p1 = *(const float2*)(row + 8);
                float2 p2 = *(const float2*)(row + 16);
                float2 p3 = *(const float2*)(row + 24);
                v.x = pack_h2(p0.x, p0.y);
                v.y = pack_h2(p1.x, p1.y);
                v.z = pack_h2(p2.x, p2.y);
                v.w = pack_h2(p3.x, p3.y);
            }
            g_c0f[(size_t)(tt * P0 + sl) * 32 + lane] = v;
        }
        return;
    }

    int t  = b / (P1C * 2);
    int rm = b - t * (P1C * 2);
    int i1 = rm >> 1;
    int i2lo = (rm & 1) * 50;

    __shared__ __align__(16) float c2t[4 * C2T_Q2_STRIDE];   // ~25.7KB

    int m  = tid & 15;                          // output m (q1,q2)
    int kp = tid >> 4;                          // r1 pair: r1 = 2kp, 2kp+1
    int q1 = m >> 2, q2 = m & 3;

    // Hoist + pack this thread's two c1 rows (r1 = 2kp, 2kp+1).
    const float* c1 = c1g + (size_t)(t * P1C + i1) * 4096;   // [r1][q1][r2]
    const float4* rA = (const float4*)(c1 + (2 * kp * 4 + q1) * 32);
    const float4* rB = (const float4*)(c1 + ((2 * kp + 1) * 4 + q1) * 32);
    unsigned long long PA[8][2], PB[8][2];
    #pragma unroll
    for (int k = 0; k < 8; k++) {
        float4 a = rA[k]; PA[k][0] = pack2(a.x, a.y); PA[k][1] = pack2(a.z, a.w);
        float4 c = rB[k]; PB[k][0] = pack2(c.x, c.y); PB[k][1] = pack2(c.z, c.w);
    }

    // Transposed+skewed c2 half-table: c2t[q2][i2'][r2] = c2[i2lo+i2'][r2][q2]
    const float* c2base = c2g + ((size_t)t * P2C + i2lo) * 128;
    for (int idx = tid; idx < 50 * 128; idx += 256) {
        int i2p = idx >> 7;
        int rr  = (idx >> 2) & 31;
        int qq  = idx & 3;
        c2t[qq * C2T_Q2_STRIDE + i2p * 32 + rr] = c2base[idx];
    }
    __syncthreads();

    // Fragment destination for this thread's half2.
    int frag   = kp >> 3;
    int lane16 = (m & 7) * 4 + (kp & 3);
    int reg    = ((m >> 3) & 1) + (((kp >> 2) & 1) << 1);
    unsigned soff = frag * 512 + lane16 * 16 + reg * 4;
    char* Wt = (char*)g_W12 + ((size_t)(t * P1C + i1) * P2C + i2lo) * 1024;

    const float* c2q = c2t + q2 * C2T_Q2_STRIDE;
    for (int i2p = 0; i2p < 50; i2p++) {
        const ulonglong2* sp = (const ulonglong2*)(c2q + i2p * 32);
        unsigned long long a0 = 0, a1 = 0, b0 = 0, b1 = 0;
        #pragma unroll
        for (int k = 0; k < 8; k++) {
            ulonglong2 s = sp[k];
            FMA_F32X2(a0, PA[k][0], s.x, a0);
            FMA_F32X2(a1, PA[k][1], s.y, a1);
            FMA_F32X2(b0, PB[k][0], s.x, b0);
            FMA_F32X2(b1, PB[k][1], s.y, b1);
        }
        float2 f0 = unpack2(a0), f1 = unpack2(a1);
        float2 f2 = unpack2(b0), f3 = unpack2(b1);
        float vlo = (f0.x + f0.y) + (f1.x + f1.y);   // W[m][2kp]
        float vhi = (f2.x + f2.y) + (f3.x + f3.y);   // W[m][2kp+1]
        *(unsigned*)(Wt + i2p * 1024 + soff) = pack_h2(vlo, vhi);
    }
}

// ---------------------------------------------------------------------------
// Kernel 2: per-bag lookup + pool via HMMA. One warp per bag.
// Per lookup: 1 shfl + 3 coalesced LDG.128 + 2 mma.m16n8k16 (f32 accum).
// ---------------------------------------------------------------------------
__global__ void tt_lookup_kernel(const int* __restrict__ indices,
                                 const int* __restrict__ offsets,
                                 float* __restrict__ out,
                                 int B, int bags_per_table) {
    int bag = (int)((blockIdx.x * (size_t)blockDim.x + threadIdx.x) >> 5);
    if (bag >= B) return;
    int lane = threadIdx.x & 31;
    int g = lane >> 2, j = lane & 3;

    int t = bag / bags_per_table;
    int s = offsets[bag], e = offsets[bag + 1];

    const uint4* Wt = (const uint4*)(g_W12 + (size_t)t * P1C * P2C * 512);
    const uint4* Cf = g_c0f + (size_t)t * P0 * 32;

    float d0 = 0.f, d1 = 0.f, d2 = 0.f, d3 = 0.f;

    for (int base = s; base < e; base += 32) {
        int n = min(32, e - base);
        int idx = (base + lane < e) ? indices[base + lane] : 0;  // coalesced
        int i0  = idx / 10000;
        int rem = idx - i0 * 10000;
        int v   = rem | (i0 << 20);            // slice id (20b) | i0 (7b)

        for (int p = 0; p < n; p++) {
            int vp = __shfl_sync(0xffffffffu, v, p);
            const uint4* wb = Wt + (vp & 0xFFFFF) * 64;
            const uint4* cb = Cf + (vp >> 20) * 32;
            uint4 A0 = wb[lane];
            uint4 A1 = wb[32 + lane];
            uint4 Bf = cb[lane];
            asm volatile(
                "mma.sync.aligned.m16n8k16.row.col.f32.f16.f16.f32 "
                "{%0,%1,%2,%3}, {%4,%5,%6,%7}, {%8,%9}, {%0,%1,%2,%3};"
                : "+f"(d0), "+f"(d1), "+f"(d2), "+f"(d3)
                : "r"(A0.x), "r"(A0.y), "r"(A0.z), "r"(A0.w),
                  "r"(Bf.x), "r"(Bf.y));
            asm volatile(
                "mma.sync.aligned.m16n8k16.row.col.f32.f16.f16.f32 "
                "{%0,%1,%2,%3}, {%4,%5,%6,%7}, {%8,%9}, {%0,%1,%2,%3};"
                : "+f"(d0), "+f"(d1), "+f"(d2), "+f"(d3)
                : "r"(A1.x), "r"(A1.y), "r"(A1.z), "r"(A1.w),
                  "r"(Bf.z), "r"(Bf.w));
        }
    }

    // D[m][q0]: d0=(g,2j) d1=(g,2j+1) d2=(g+8,2j) d3=(g+8,2j+1);
    // out[bag][q0*16 + m]; only cols 0..3 valid -> lanes with j<2 write.
    if (j < 2) {
        float* ob = out + (size_t)bag * 64;
        ob[(2 * j) * 16 + g]         = d0;
        ob[(2 * j + 1) * 16 + g]     = d1;
        ob[(2 * j) * 16 + g + 8]     = d2;
        ob[(2 * j + 1) * 16 + g + 8] = d3;
    }
}

// ---------------------------------------------------------------------------
extern "C" void kernel_launch(void* const* d_in, const int* in_sizes, int n_in,
                              void* d_out, int out_size) {
    const int* indices = (const int*)d_in[0];
    const int* offsets = (const int*)d_in[1];
    const float* c0 = (const float*)d_in[2];
    const float* c1 = (const float*)d_in[3];
    const float* c2 = (const float*)d_in[4];

    int B = in_sizes[1] - 1;
    int bags_per_table = B / NT;

    tt_precompute_kernel<<<NT * P1C * 2 + NT, 256>>>(c1, c2, c0);

    const int warps_per_block = 8;
    int blocks = (B + warps_per_block - 1) / warps_per_block;
    tt_lookup_kernel<<<blocks, warps_per_block * 32>>>(
        indices, offsets, (float*)d_out, B, bags_per_table);
}